// round 10
// baseline (speedup 1.0000x reference)
#include <cuda_runtime.h>
#include <cstdint>

#define BB 64
#define NN 10000
#define LL 50
#define DD 512
#define OO 7
#define KNB 10
#define NGRP 5        // ligand groups per batch (10 ligs each)
#define GL 10         // ligs per group
#define NPAIR 5       // packed lig pairs
#define NHALF 2       // point-cloud halves per (b,grp)
#define HPTS 5000     // points per half
#define NCHUNK 4      // chunks (= warps) per block
#define CHUNK 1250    // HPTS / NCHUNK
#define SITER 10      // Phase-A sample iterations (320 pts of 1250)
#define CAPS 160      // smem candidate capacity per lig (per half)
#define NWORD 313     // ceil(NN/32)
#define QB 8          // pool blocks per batch
#define OTILE 64      // gemv output tile
#define FULLM 0xffffffffu

typedef unsigned long long ull;

// -------- device scratch (no allocations allowed) --------
__device__ ull   g_top[BB * LL * NHALF * KNB];   // per-half top-10 (enc|idx)
__device__ int   g_ucnt[BB];
__device__ float g_part[BB * QB * DD];
__device__ float g_h[BB * DD];

// order-preserving float-bits->uint transform (handles negative keys)
__device__ __forceinline__ unsigned encbits(unsigned u) {
    unsigned msk = (unsigned)((int)u >> 31) | 0x80000000u;
    return u ^ msk;
}
// key = 0.5*|p|^2 - p.l  (order-equivalent to |p-l|^2 for fixed l)
__device__ __forceinline__ float qof(float px, float py, float pz) {
    return 0.5f * __fmaf_rn(pz, pz, __fmaf_rn(py, py, __fmul_rn(px, px)));
}
__device__ __forceinline__ float keyf(float px, float py, float pz, float q,
                                      float lx, float ly, float lz) {
    return __fmaf_rn(pz, -lz, __fmaf_rn(py, -ly, __fmaf_rn(px, -lx, q)));
}
__device__ __forceinline__ ull umin64(ull a, ull b) { return a < b ? a : b; }
__device__ __forceinline__ ull umax64(ull a, ull b) { return a < b ? b : a; }

// ---- packed f32x2 helpers (sm_100+) ----
__device__ __forceinline__ ull pack2(float a, float b) {
    ull r;
    asm("mov.b64 %0, {%1, %2};" : "=l"(r) : "f"(a), "f"(b));
    return r;
}
__device__ __forceinline__ void unpack2(ull v, float& a, float& b) {
    asm("mov.b64 {%0, %1}, %2;" : "=f"(a), "=f"(b) : "l"(v));
}
__device__ __forceinline__ ull fma2(ull a, ull b, ull c) {
    ull d;
    asm("fma.rn.f32x2 %0, %1, %2, %3;" : "=l"(d) : "l"(a), "l"(b), "l"(c));
    return d;
}

// branch-free, vote-free candidate insert: if key<=thr, append (idx,keybits)
__device__ __forceinline__ void cand_insert(float key, float thr, int i,
                                            unsigned ca, unsigned ba) {
    unsigned kb = __float_as_uint(key);
    asm volatile(
        "{\n\t"
        ".reg .pred p;\n\t"
        ".reg .u32 r, a;\n\t"
        "setp.le.f32 p, %0, %1;\n\t"
        "@p atom.shared.add.u32 r, [%2], 1;\n\t"
        "@p setp.lt.and.u32 p, r, %5, p;\n\t"
        "@p mad.lo.u32 a, r, 8, %3;\n\t"
        "@p st.shared.v2.u32 [a], {%4, %6};\n\t"
        "}"
        :: "f"(key), "f"(thr), "r"(ca), "r"(ba), "r"(i), "n"(CAPS), "r"(kb)
        : "memory");
}

// full 32-lane bitonic sort, ascending (float)
__device__ __forceinline__ float bitonic_f(float v, int lane) {
#pragma unroll
    for (int k = 2; k <= 32; k <<= 1) {
#pragma unroll
        for (int o = k >> 1; o; o >>= 1) {
            float p = __shfl_xor_sync(FULLM, v, o);
            bool keepMin = (((lane & o) == 0) == ((lane & k) == 0));
            v = keepMin ? fminf(v, p) : fmaxf(v, p);
        }
    }
    return v;
}
// full 32-lane bitonic sort, ascending (u64)
__device__ __forceinline__ ull bitonic_u64(ull v, int lane) {
#pragma unroll
    for (int k = 2; k <= 32; k <<= 1) {
#pragma unroll
        for (int o = k >> 1; o; o >>= 1) {
            ull p = __shfl_xor_sync(FULLM, v, o);
            bool keepMin = (((lane & o) == 0) == ((lane & k) == 0));
            v = keepMin ? umin64(v, p) : umax64(v, p);
        }
    }
    return v;
}

// ===================== K1: fused threshold + collect + select =============
// block = (batch, ligand-group, half); warp w = chunk w of the half.
// Phase A samples only the first 320 pts/chunk: the 10th-smallest of any
// subset is a provable upper bound on the chunk's true 10th-smallest.
__global__ void __launch_bounds__(NCHUNK * 32, 5)
k_knn(const float* __restrict__ pos, const float* __restrict__ lig) {
    int bg   = blockIdx.x >> 1;
    int half = blockIdx.x & 1;
    int b    = bg / NGRP;
    int grp  = bg % NGRP;
    int tid  = threadIdx.x;
    int ch   = tid >> 5;          // warp = chunk
    int lane = tid & 31;

    __shared__ float s_bound[NCHUNK * GL];
    __shared__ int   s_cnt[GL];
    __shared__ ull   s_cand[GL][CAPS];

    if (tid < GL) s_cnt[tid] = 0;

    // packed NEGATED ligand coords: pair p holds ligs (2p, 2p+1)
    ull nlx2[NPAIR], nly2[NPAIR], nlz2[NPAIR];
    const float* lp = lig + ((size_t)b * LL + grp * GL) * 3;
#pragma unroll
    for (int p = 0; p < NPAIR; p++) {
        nlx2[p] = pack2(-lp[(2 * p) * 3 + 0], -lp[(2 * p + 1) * 3 + 0]);
        nly2[p] = pack2(-lp[(2 * p) * 3 + 1], -lp[(2 * p + 1) * 3 + 1]);
        nlz2[p] = pack2(-lp[(2 * p) * 3 + 2], -lp[(2 * p + 1) * 3 + 2]);
    }

    const float* pp = pos + (size_t)b * NN * 3;
    const int i0 = half * HPTS + ch * CHUNK;

    // ---- Phase A (sampled): lane minima over first 320 pts of chunk ----
    float m[GL];
#pragma unroll
    for (int j = 0; j < GL; j++) m[j] = 3.4e38f;
#pragma unroll 2
    for (int s = 0; s < SITER; s++) {
        int i = i0 + s * 32 + lane;
        float px = pp[3 * i + 0], py = pp[3 * i + 1], pz = pp[3 * i + 2];
        float q = qof(px, py, pz);
        ull px2 = pack2(px, px), py2 = pack2(py, py);
        ull pz2 = pack2(pz, pz), q2 = pack2(q, q);
#pragma unroll
        for (int p = 0; p < NPAIR; p++) {
            ull k2 = fma2(pz2, nlz2[p], fma2(py2, nly2[p], fma2(px2, nlx2[p], q2)));
            float k0, k1; unpack2(k2, k0, k1);
            m[2 * p]     = fminf(m[2 * p], k0);
            m[2 * p + 1] = fminf(m[2 * p + 1], k1);
        }
    }
    // 10 distinct lanes (=> 10 distinct sample points) have minima <=
    // sorted[9]: valid upper bound on the chunk's (and sample's) 10th key.
#pragma unroll
    for (int j = 0; j < GL; j++) {
        float sv = bitonic_f(m[j], lane);
        float w  = __shfl_sync(FULLM, sv, KNB - 1);
        if (lane == 0) s_bound[ch * GL + j] = w;
    }
    __syncthreads();

    // ---- Phase B: T0 = min over this half's chunks; predicated collect ----
    float t[GL];
#pragma unroll
    for (int j = 0; j < GL; j++) {
        float tv = s_bound[j];
#pragma unroll
        for (int c = 1; c < NCHUNK; c++) tv = fminf(tv, s_bound[c * GL + j]);
        t[j] = tv;
    }
    unsigned cb = (unsigned)__cvta_generic_to_shared(s_cnt);
    unsigned bb = (unsigned)__cvta_generic_to_shared(&s_cand[0][0]);

    // 39 clean iterations; tail handled separately
    for (int s = 0; s < 39; s++) {
        int i = i0 + s * 32 + lane;
        float px = pp[3 * i + 0], py = pp[3 * i + 1], pz = pp[3 * i + 2];
        float q = qof(px, py, pz);
        ull px2 = pack2(px, px), py2 = pack2(py, py);
        ull pz2 = pack2(pz, pz), q2 = pack2(q, q);
#pragma unroll
        for (int p = 0; p < NPAIR; p++) {
            ull k2 = fma2(pz2, nlz2[p], fma2(py2, nly2[p], fma2(px2, nlx2[p], q2)));
            float k0, k1; unpack2(k2, k0, k1);
            int ja = 2 * p, jb = 2 * p + 1;
            cand_insert(k0, t[ja], i, cb + 4u * ja, bb + (unsigned)(ja * CAPS * 8));
            cand_insert(k1, t[jb], i, cb + 4u * jb, bb + (unsigned)(jb * CAPS * 8));
        }
    }
    {   // tail iteration: only lanes with 1248+lane < 1250 are live
        int i = i0 + 39 * 32 + lane;
        bool valid = (39 * 32 + lane) < CHUNK;
        int ic = valid ? i : i0;
        float px = pp[3 * ic + 0], py = pp[3 * ic + 1], pz = pp[3 * ic + 2];
        float q = qof(px, py, pz);
        ull px2 = pack2(px, px), py2 = pack2(py, py);
        ull pz2 = pack2(pz, pz), q2 = pack2(q, q);
#pragma unroll
        for (int p = 0; p < NPAIR; p++) {
            ull k2 = fma2(pz2, nlz2[p], fma2(py2, nly2[p], fma2(px2, nlx2[p], q2)));
            float k0, k1; unpack2(k2, k0, k1);
            if (!valid) { k0 = 3.4e38f; k1 = 3.4e38f; }
            int ja = 2 * p, jb = 2 * p + 1;
            cand_insert(k0, t[ja], i, cb + 4u * ja, bb + (unsigned)(ja * CAPS * 8));
            cand_insert(k1, t[jb], i, cb + 4u * jb, bb + (unsigned)(jb * CAPS * 8));
        }
    }
    __syncthreads();

    // ---- Phase C: warps cooperatively select exact top-10 per lig ----
    for (int j = ch; j < GL; j += NCHUNK) {
        int cnt = s_cnt[j];
        int base_out = (((b * LL + grp * GL + j) * NHALF) + half) * KNB;

        if (cnt <= CAPS) {
            // running sorted-32 accumulator via bitonic merge
            ull cur = ~0ull;
            for (int s0 = 0; s0 < cnt; s0 += 32) {   // cnt warp-uniform
                int s = s0 + lane;
                ull v = ~0ull;
                if (s < cnt) {
                    ull raw = s_cand[j][s];          // low = idx, high = keybits
                    unsigned kb = (unsigned)(raw >> 32);
                    v = ((ull)encbits(kb) << 32) | (unsigned)(raw & 0xffffffffu);
                }
                v = bitonic_u64(v, lane);                        // new asc
                ull rv = __shfl_sync(FULLM, v, 31 - lane);       // new desc
                cur = umin64(cur, rv);                           // low-32
#pragma unroll
                for (int o = 16; o; o >>= 1) {                   // re-sort asc
                    ull p = __shfl_xor_sync(FULLM, cur, o);
                    cur = ((lane & o) == 0) ? umin64(cur, p) : umax64(cur, p);
                }
            }
            if (lane < KNB) g_top[base_out + lane] = cur;
        } else {
            // fallback: exact rescan of this half (not expected to trigger)
            const float* lq = lig + ((size_t)b * LL + grp * GL + j) * 3;
            float flx = lq[0], fly = lq[1], flz = lq[2];
            ull hp[KNB];
#pragma unroll
            for (int r = 0; r < KNB; r++) hp[r] = ~0ull;
            for (int i = half * HPTS + lane; i < half * HPTS + HPTS; i += 32) {
                float px = pp[3 * i + 0], py = pp[3 * i + 1], pz = pp[3 * i + 2];
                float q = qof(px, py, pz);
                unsigned kb = __float_as_uint(keyf(px, py, pz, q, flx, fly, flz));
                ull v = ((ull)encbits(kb) << 32) | (unsigned)i;
                if (v < hp[KNB - 1]) {
#pragma unroll
                    for (int r = 0; r < KNB; r++)
                        if (v < hp[r]) { ull tm = hp[r]; hp[r] = v; v = tm; }
                }
            }
            ull curv = hp[0];
#pragma unroll
            for (int rr = 0; rr < KNB; rr++) {
                ull w = curv;
#pragma unroll
                for (int o = 16; o; o >>= 1)
                    w = umin64(w, __shfl_xor_sync(FULLM, w, o));
                if (lane == 0) g_top[base_out + rr] = w;
                if (curv == w) {
#pragma unroll
                    for (int r = 0; r < KNB - 1; r++) hp[r] = hp[r + 1];
                    hp[KNB - 1] = ~0ull;
                    curv = hp[0];
                }
            }
        }
    }
}

// ===================== K2: merge halves + dedupe + wide gather ============
// 512 threads = 16 warps. Merge per-half top-10s from g_top straight into
// the dedupe bitmap (redundantly per block - cheap), then gather a quarter.
__global__ void __launch_bounds__(DD)
k_pool(const float* __restrict__ x) {
    int blk = blockIdx.x;
    int b = blk / QB, q = blk % QB;
    int tid = threadIdx.x;
    int lane = tid & 31, wid = tid >> 5;
    int sub = tid >> 7;       // 0..3
    int t4  = tid & 127;      // float4 feature group

    __shared__ unsigned bits[320];
    __shared__ int   wsum[16];
    __shared__ int   s_list[512];
    __shared__ int   s_total;
    __shared__ float4 s_acc[4][128];

    if (tid < 320) bits[tid] = 0u;
    __syncthreads();

    // ---- merge NHALF*KNB per-half winners -> exact top-10 -> bitmap ----
    for (int l = wid; l < LL; l += 16) {
        ull v = (lane < NHALF * KNB) ? g_top[((size_t)b * LL + l) * NHALF * KNB + lane]
                                     : ~0ull;
        v = bitonic_u64(v, lane);
        if (lane < KNB) {
            unsigned idx = (unsigned)(v & 0xffffffffu);
            atomicOr(&bits[idx >> 5], 1u << (idx & 31));
        }
    }
    __syncthreads();

    // ---- prefix scan of bitmap popcounts -> compact unique list ----
    int c = (tid < NWORD) ? __popc(bits[tid]) : 0;
    int sc = c;  // inclusive warp scan
#pragma unroll
    for (int o = 1; o < 32; o <<= 1) {
        int n = __shfl_up_sync(FULLM, sc, o);
        if (lane >= o) sc += n;
    }
    if (lane == 31) wsum[wid] = sc;
    __syncthreads();
    if (tid < 16) {
        int w = wsum[tid], sw = w;
#pragma unroll
        for (int o = 1; o < 16; o <<= 1) {
            int n = __shfl_up_sync(0x0000ffffu, sw, o);
            if (tid >= o) sw += n;
        }
        wsum[tid] = sw - w;               // exclusive warp offsets
        if (tid == 15) s_total = sw;
    }
    __syncthreads();
    if (tid < NWORD) {
        int p = wsum[wid] + sc - c;
        unsigned mm = bits[tid];
        while (mm) {
            int bp = __ffs(mm) - 1; mm &= mm - 1;
            s_list[p++] = tid * 32 + bp;
        }
    }
    __syncthreads();
    int cnt = s_total;
    if (q == 0 && tid == 0) g_ucnt[b] = cnt;

    // ---- this block's row range; sub-groups stride alternate rows ----
    int per = (cnt + QB - 1) / QB;
    int j0 = q * per;
    int j1 = min(cnt, j0 + per);

    const float* xb = x + (size_t)b * NN * DD;
    float4 acc = make_float4(0.f, 0.f, 0.f, 0.f);
#pragma unroll 4
    for (int j = j0 + sub; j < j1; j += 4) {
        const float4* row = reinterpret_cast<const float4*>(xb + (size_t)s_list[j] * DD);
        float4 v = row[t4];
        acc.x += v.x; acc.y += v.y; acc.z += v.z; acc.w += v.w;
    }
    s_acc[sub][t4] = acc;
    __syncthreads();

    if (sub == 0) {
        float4 a0 = s_acc[0][t4], a1 = s_acc[1][t4];
        float4 a2 = s_acc[2][t4], a3 = s_acc[3][t4];
        float4 r;
        r.x = (a0.x + a1.x) + (a2.x + a3.x);
        r.y = (a0.y + a1.y) + (a2.y + a3.y);
        r.z = (a0.z + a1.z) + (a2.z + a3.z);
        r.w = (a0.w + a1.w) + (a2.w + a3.w);
        reinterpret_cast<float4*>(g_part + (size_t)(b * QB + q) * DD)[t4] = r;
    }
}

// ===================== K3: GEMV h = emb @ W1 + b1 (float4 weights) ========
// block = (batch, otile of 64); 256 threads = 16 o4-groups x 16 k-slices(32)
__global__ void __launch_bounds__(256)
k_gemv(const float* __restrict__ W1, const float* __restrict__ b1) {
    int blk = blockIdx.x;
    int b  = blk >> 3;           // 8 otiles per batch
    int qo = blk & 7;
    int tid = threadIdx.x;
    int og = tid & 15;           // float4 output group (4 outputs)
    int ks = tid >> 4;           // k-slice of 32

    __shared__ float  s_v[DD];
    __shared__ float4 s_p[16][16];   // [kslice][ogroup]

    // emb for this batch
    float cnt = (float)g_ucnt[b];
    const float* pp = g_part + (size_t)b * QB * DD;
    for (int f = tid; f < DD; f += 256) {
        float e = 0.f;
#pragma unroll
        for (int q = 0; q < QB; q++) e += pp[q * DD + f];
        s_v[f] = e / cnt;
    }
    __syncthreads();

    // partial GEMV: 32 float4 loads per thread
    int j0 = qo * OTILE;
    const float* vv = s_v + ks * 32;
    const float* wbase = W1 + (size_t)(ks * 32) * DD + j0 + og * 4;
    float4 acc = make_float4(0.f, 0.f, 0.f, 0.f);
#pragma unroll 8
    for (int k = 0; k < 32; k++) {
        float4 w = *reinterpret_cast<const float4*>(wbase + (size_t)k * DD);
        float sv = vv[k];
        acc.x = __fmaf_rn(sv, w.x, acc.x);
        acc.y = __fmaf_rn(sv, w.y, acc.y);
        acc.z = __fmaf_rn(sv, w.z, acc.z);
        acc.w = __fmaf_rn(sv, w.w, acc.w);
    }
    s_p[ks][og] = acc;
    __syncthreads();

    if (tid < OTILE) {
        int cc = tid & 3, g = tid >> 2;
        float h = 0.f;
#pragma unroll
        for (int s = 0; s < 16; s++)
            h += reinterpret_cast<const float*>(&s_p[s][g])[cc];
        g_h[b * DD + j0 + tid] = h + b1[j0 + tid];
    }
}

// -------- block-wide sum over 512 threads --------
__device__ __forceinline__ float block_sum512(float v, float* s_red) {
    int tid = threadIdx.x;
#pragma unroll
    for (int o = 16; o; o >>= 1) v += __shfl_xor_sync(FULLM, v, o);
    if ((tid & 31) == 0) s_red[tid >> 5] = v;
    __syncthreads();
    if (tid < 16) {
        float r = s_red[tid];
#pragma unroll
        for (int o = 8; o; o >>= 1) r += __shfl_xor_sync(0x0000ffffu, r, o);
        if (tid == 0) s_red[0] = r;
    }
    __syncthreads();
    float r = s_red[0];
    __syncthreads();
    return r;
}

// ===================== K4: LN + SiLU + head ===============================
__global__ void __launch_bounds__(DD)
k_lnhead(const float* __restrict__ gamma, const float* __restrict__ beta,
         const float* __restrict__ W2, const float* __restrict__ b2,
         float* __restrict__ out) {
    int b = blockIdx.x, tid = threadIdx.x;
    __shared__ float s_red[16];
    __shared__ float s_part[16][OO];

    float h = g_h[b * DD + tid];

    float mu  = block_sum512(h, s_red) * (1.0f / DD);
    float dv  = h - mu;
    float var = block_sum512(dv * dv, s_red) * (1.0f / DD);
    float vn  = dv * rsqrtf(var + 1e-5f) * gamma[tid] + beta[tid];
    float act = vn / (1.0f + __expf(-vn));  // SiLU

    float p[OO];
#pragma unroll
    for (int o = 0; o < OO; o++) p[o] = act * W2[tid * OO + o];
#pragma unroll
    for (int o = 0; o < OO; o++)
#pragma unroll
        for (int of = 16; of; of >>= 1)
            p[o] += __shfl_xor_sync(FULLM, p[o], of);
    if ((tid & 31) == 0) {
#pragma unroll
        for (int o = 0; o < OO; o++) s_part[tid >> 5][o] = p[o];
    }
    __syncthreads();
    if (tid < OO) {
        float s = 0.f;
#pragma unroll
        for (int w = 0; w < 16; w++) s += s_part[w][tid];
        out[b * OO + tid] = s + b2[tid];
    }
}

extern "C" void kernel_launch(void* const* d_in, const int* in_sizes, int n_in,
                              void* d_out, int out_size) {
    const float* pos   = (const float*)d_in[0];
    const float* x     = (const float*)d_in[1];
    const float* lig   = (const float*)d_in[2];
    const float* W1    = (const float*)d_in[3];
    const float* b1    = (const float*)d_in[4];
    const float* gamma = (const float*)d_in[5];
    const float* beta  = (const float*)d_in[6];
    const float* W2    = (const float*)d_in[7];
    const float* b2    = (const float*)d_in[8];
    float* out = (float*)d_out;

    k_knn<<<BB * NGRP * NHALF, NCHUNK * 32>>>(pos, lig);  // 640 x 128
    k_pool<<<BB * QB, DD>>>(x);                           // 512 x 512
    k_gemv<<<BB * 8, 256>>>(W1, b1);                      // 512 x 256
    k_lnhead<<<BB, DD>>>(gamma, beta, W2, b2, out);
}

// round 11
// speedup vs baseline: 2.3999x; 2.3999x over previous
#include <cuda_runtime.h>
#include <cstdint>

#define BB 64
#define NN 10000
#define LL 50
#define DD 512
#define OO 7
#define KNB 10
#define NGRP 5        // ligand groups per batch (10 ligs each)
#define GL 10         // ligs per group
#define NPAIR 5       // packed lig pairs
#define NHALF 2       // point-cloud halves per (b,grp)
#define HPTS 5000     // points per half
#define NCHUNK 4      // chunks (= warps) per block
#define CHUNK 1250    // HPTS / NCHUNK
#define CAPS 160      // smem candidate capacity per lig (per half)
#define NWORD 313     // ceil(NN/32)
#define QB 8          // pool blocks per batch
#define OTILE 64      // gemv output tile
#define FULLM 0xffffffffu

typedef unsigned long long ull;

// -------- device scratch (no allocations allowed) --------
__device__ ull   g_top[BB * LL * NHALF * KNB];   // per-half top-10 (enc|idx)
__device__ int   g_sel10[BB * LL * KNB];
__device__ int   g_ucnt[BB];
__device__ float g_part[BB * QB * DD];
__device__ float g_h[BB * DD];

// order-preserving float-bits->uint transform (handles negative keys)
__device__ __forceinline__ unsigned encbits(unsigned u) {
    unsigned msk = (unsigned)((int)u >> 31) | 0x80000000u;
    return u ^ msk;
}
// key = 0.5*|p|^2 - p.l  (order-equivalent to |p-l|^2 for fixed l)
__device__ __forceinline__ float qof(float px, float py, float pz) {
    return 0.5f * __fmaf_rn(pz, pz, __fmaf_rn(py, py, __fmul_rn(px, px)));
}
__device__ __forceinline__ float keyf(float px, float py, float pz, float q,
                                      float lx, float ly, float lz) {
    return __fmaf_rn(pz, -lz, __fmaf_rn(py, -ly, __fmaf_rn(px, -lx, q)));
}
__device__ __forceinline__ ull umin64(ull a, ull b) { return a < b ? a : b; }
__device__ __forceinline__ ull umax64(ull a, ull b) { return a < b ? b : a; }

// ---- packed f32x2 helpers (sm_100+) ----
__device__ __forceinline__ ull pack2(float a, float b) {
    ull r;
    asm("mov.b64 %0, {%1, %2};" : "=l"(r) : "f"(a), "f"(b));
    return r;
}
__device__ __forceinline__ void unpack2(ull v, float& a, float& b) {
    asm("mov.b64 {%0, %1}, %2;" : "=f"(a), "=f"(b) : "l"(v));
}
__device__ __forceinline__ ull fma2(ull a, ull b, ull c) {
    ull d;
    asm("fma.rn.f32x2 %0, %1, %2, %3;" : "=l"(d) : "l"(a), "l"(b), "l"(c));
    return d;
}

// branch-free, vote-free candidate insert: if key<=thr, append (idx,keybits)
__device__ __forceinline__ void cand_insert(float key, float thr, int i,
                                            unsigned ca, unsigned ba) {
    unsigned kb = __float_as_uint(key);
    asm volatile(
        "{\n\t"
        ".reg .pred p;\n\t"
        ".reg .u32 r, a;\n\t"
        "setp.le.f32 p, %0, %1;\n\t"
        "@p atom.shared.add.u32 r, [%2], 1;\n\t"
        "@p setp.lt.and.u32 p, r, %5, p;\n\t"
        "@p mad.lo.u32 a, r, 8, %3;\n\t"
        "@p st.shared.v2.u32 [a], {%4, %6};\n\t"
        "}"
        :: "f"(key), "f"(thr), "r"(ca), "r"(ba), "r"(i), "n"(CAPS), "r"(kb)
        : "memory");
}

// full 32-lane bitonic sort, ascending (float)
__device__ __forceinline__ float bitonic_f(float v, int lane) {
#pragma unroll
    for (int k = 2; k <= 32; k <<= 1) {
#pragma unroll
        for (int o = k >> 1; o; o >>= 1) {
            float p = __shfl_xor_sync(FULLM, v, o);
            bool keepMin = (((lane & o) == 0) == ((lane & k) == 0));
            v = keepMin ? fminf(v, p) : fmaxf(v, p);
        }
    }
    return v;
}
// full 32-lane bitonic sort, ascending (u64)
__device__ __forceinline__ ull bitonic_u64(ull v, int lane) {
#pragma unroll
    for (int k = 2; k <= 32; k <<= 1) {
#pragma unroll
        for (int o = k >> 1; o; o >>= 1) {
            ull p = __shfl_xor_sync(FULLM, v, o);
            bool keepMin = (((lane & o) == 0) == ((lane & k) == 0));
            v = keepMin ? umin64(v, p) : umax64(v, p);
        }
    }
    return v;
}

// ===================== K1: fused threshold + collect + select =============
// block = (batch, ligand-group, half); warp w = chunk w of the half.
__global__ void __launch_bounds__(NCHUNK * 32, 5)
k_knn(const float* __restrict__ pos, const float* __restrict__ lig) {
    int bg   = blockIdx.x >> 1;
    int half = blockIdx.x & 1;
    int b    = bg / NGRP;
    int grp  = bg % NGRP;
    int tid  = threadIdx.x;
    int ch   = tid >> 5;          // warp = chunk
    int lane = tid & 31;

    __shared__ float s_bound[NCHUNK * GL];
    __shared__ int   s_cnt[GL];
    __shared__ ull   s_cand[GL][CAPS];

    if (tid < GL) s_cnt[tid] = 0;

    // packed NEGATED ligand coords: pair p holds ligs (2p, 2p+1)
    ull nlx2[NPAIR], nly2[NPAIR], nlz2[NPAIR];
    const float* lp = lig + ((size_t)b * LL + grp * GL) * 3;
#pragma unroll
    for (int p = 0; p < NPAIR; p++) {
        nlx2[p] = pack2(-lp[(2 * p) * 3 + 0], -lp[(2 * p + 1) * 3 + 0]);
        nly2[p] = pack2(-lp[(2 * p) * 3 + 1], -lp[(2 * p + 1) * 3 + 1]);
        nlz2[p] = pack2(-lp[(2 * p) * 3 + 2], -lp[(2 * p + 1) * 3 + 2]);
    }

    const float* pp = pos + (size_t)b * NN * 3;
    const int i0 = half * HPTS + ch * CHUNK, i1 = i0 + CHUNK;

    // ---- Phase A: per-chunk lane minima over the FULL chunk ----
    float m[GL];
#pragma unroll
    for (int j = 0; j < GL; j++) m[j] = 3.4e38f;
    for (int i = i0 + lane; i < i1; i += 32) {
        float px = pp[3 * i + 0], py = pp[3 * i + 1], pz = pp[3 * i + 2];
        float q = qof(px, py, pz);
        ull px2 = pack2(px, px), py2 = pack2(py, py);
        ull pz2 = pack2(pz, pz), q2 = pack2(q, q);
#pragma unroll
        for (int p = 0; p < NPAIR; p++) {
            ull k2 = fma2(pz2, nlz2[p], fma2(py2, nly2[p], fma2(px2, nlx2[p], q2)));
            float k0, k1; unpack2(k2, k0, k1);
            m[2 * p]     = fminf(m[2 * p], k0);
            m[2 * p + 1] = fminf(m[2 * p + 1], k1);
        }
    }
    // 10 distinct lanes (=> 10 distinct points) have minima <= sorted[9]:
    // provable upper bound on this chunk's 10th-smallest key.
#pragma unroll
    for (int j = 0; j < GL; j++) {
        float sv = bitonic_f(m[j], lane);
        float w  = __shfl_sync(FULLM, sv, KNB - 1);
        if (lane == 0) s_bound[ch * GL + j] = w;
    }
    __syncthreads();

    // ---- Phase B: T0 = min over this half's chunks; predicated collect ----
    float t[GL];
#pragma unroll
    for (int j = 0; j < GL; j++) {
        float tv = s_bound[j];
#pragma unroll
        for (int c = 1; c < NCHUNK; c++) tv = fminf(tv, s_bound[c * GL + j]);
        t[j] = tv;
    }
    unsigned cb = (unsigned)__cvta_generic_to_shared(s_cnt);
    unsigned bb = (unsigned)__cvta_generic_to_shared(&s_cand[0][0]);

    // 39 clean iterations; tail handled separately
    for (int s = 0; s < 39; s++) {
        int i = i0 + s * 32 + lane;
        float px = pp[3 * i + 0], py = pp[3 * i + 1], pz = pp[3 * i + 2];
        float q = qof(px, py, pz);
        ull px2 = pack2(px, px), py2 = pack2(py, py);
        ull pz2 = pack2(pz, pz), q2 = pack2(q, q);
#pragma unroll
        for (int p = 0; p < NPAIR; p++) {
            ull k2 = fma2(pz2, nlz2[p], fma2(py2, nly2[p], fma2(px2, nlx2[p], q2)));
            float k0, k1; unpack2(k2, k0, k1);
            int ja = 2 * p, jb = 2 * p + 1;
            cand_insert(k0, t[ja], i, cb + 4u * ja, bb + (unsigned)(ja * CAPS * 8));
            cand_insert(k1, t[jb], i, cb + 4u * jb, bb + (unsigned)(jb * CAPS * 8));
        }
    }
    {   // tail iteration: only lanes with 1248+lane < 1250 are live
        int i = i0 + 39 * 32 + lane;
        bool valid = (39 * 32 + lane) < CHUNK;
        int ic = valid ? i : i0;
        float px = pp[3 * ic + 0], py = pp[3 * ic + 1], pz = pp[3 * ic + 2];
        float q = qof(px, py, pz);
        ull px2 = pack2(px, px), py2 = pack2(py, py);
        ull pz2 = pack2(pz, pz), q2 = pack2(q, q);
#pragma unroll
        for (int p = 0; p < NPAIR; p++) {
            ull k2 = fma2(pz2, nlz2[p], fma2(py2, nly2[p], fma2(px2, nlx2[p], q2)));
            float k0, k1; unpack2(k2, k0, k1);
            if (!valid) { k0 = 3.4e38f; k1 = 3.4e38f; }
            int ja = 2 * p, jb = 2 * p + 1;
            cand_insert(k0, t[ja], i, cb + 4u * ja, bb + (unsigned)(ja * CAPS * 8));
            cand_insert(k1, t[jb], i, cb + 4u * jb, bb + (unsigned)(jb * CAPS * 8));
        }
    }
    __syncthreads();

    // ---- Phase C: warps cooperatively select exact top-10 per lig ----
    for (int j = ch; j < GL; j += NCHUNK) {
        int cnt = s_cnt[j];
        int base_out = (((b * LL + grp * GL + j) * NHALF) + half) * KNB;

        if (cnt <= CAPS) {
            // running sorted-32 accumulator via bitonic merge
            ull cur = ~0ull;
            for (int s0 = 0; s0 < cnt; s0 += 32) {   // cnt warp-uniform
                int s = s0 + lane;
                ull v = ~0ull;
                if (s < cnt) {
                    ull raw = s_cand[j][s];          // low = idx, high = keybits
                    unsigned kb = (unsigned)(raw >> 32);
                    v = ((ull)encbits(kb) << 32) | (unsigned)(raw & 0xffffffffu);
                }
                v = bitonic_u64(v, lane);                        // new asc
                ull rv = __shfl_sync(FULLM, v, 31 - lane);       // new desc
                cur = umin64(cur, rv);                           // low-32
#pragma unroll
                for (int o = 16; o; o >>= 1) {                   // re-sort asc
                    ull p = __shfl_xor_sync(FULLM, cur, o);
                    cur = ((lane & o) == 0) ? umin64(cur, p) : umax64(cur, p);
                }
            }
            if (lane < KNB) g_top[base_out + lane] = cur;
        } else {
            // fallback: exact rescan of this half (not expected to trigger)
            const float* lq = lig + ((size_t)b * LL + grp * GL + j) * 3;
            float flx = lq[0], fly = lq[1], flz = lq[2];
            ull hp[KNB];
#pragma unroll
            for (int r = 0; r < KNB; r++) hp[r] = ~0ull;
            for (int i = half * HPTS + lane; i < half * HPTS + HPTS; i += 32) {
                float px = pp[3 * i + 0], py = pp[3 * i + 1], pz = pp[3 * i + 2];
                float q = qof(px, py, pz);
                unsigned kb = __float_as_uint(keyf(px, py, pz, q, flx, fly, flz));
                ull v = ((ull)encbits(kb) << 32) | (unsigned)i;
                if (v < hp[KNB - 1]) {
#pragma unroll
                    for (int r = 0; r < KNB; r++)
                        if (v < hp[r]) { ull tm = hp[r]; hp[r] = v; v = tm; }
                }
            }
            ull curv = hp[0];
#pragma unroll
            for (int rr = 0; rr < KNB; rr++) {
                ull w = curv;
#pragma unroll
                for (int o = 16; o; o >>= 1)
                    w = umin64(w, __shfl_xor_sync(FULLM, w, o));
                if (lane == 0) g_top[base_out + rr] = w;
                if (curv == w) {
#pragma unroll
                    for (int r = 0; r < KNB - 1; r++) hp[r] = hp[r + 1];
                    hp[KNB - 1] = ~0ull;
                    curv = hp[0];
                }
            }
        }
    }
}

// ===================== K2: merge per-half top-10s -> exact top-10 =========
__global__ void __launch_bounds__(256)
k_top_merge() {
    int wg   = (blockIdx.x * blockDim.x + threadIdx.x) >> 5;  // (b,lig) pair
    int lane = threadIdx.x & 31;
    if (wg >= BB * LL) return;
    ull v = (lane < NHALF * KNB) ? g_top[wg * NHALF * KNB + lane] : ~0ull;
    v = bitonic_u64(v, lane);
    if (lane < KNB)
        g_sel10[wg * KNB + lane] = (int)(unsigned)(v & 0xffffffffu);
}

// ===================== K3: dedupe + wide gather (QB blocks/batch) =========
// 512 threads = 4 sub-groups x 128 threads; thread handles 4 features (float4)
__global__ void __launch_bounds__(DD)
k_pool(const float* __restrict__ x) {
    int blk = blockIdx.x;
    int b = blk / QB, q = blk % QB;
    int tid = threadIdx.x;
    int lane = tid & 31, wid = tid >> 5;
    int sub = tid >> 7;       // 0..3
    int t4  = tid & 127;      // float4 feature group

    __shared__ unsigned bits[320];
    __shared__ int   wsum[16];
    __shared__ int   s_list[512];
    __shared__ int   s_total;
    __shared__ float4 s_acc[4][128];

    // ---- dedupe 500 indices via bitmap + prefix scan (deterministic) ----
    if (tid < 320) bits[tid] = 0u;
    __syncthreads();
    if (tid < LL * KNB) {
        unsigned idx = (unsigned)g_sel10[b * LL * KNB + tid];
        atomicOr(&bits[idx >> 5], 1u << (idx & 31));
    }
    __syncthreads();

    int c = (tid < NWORD) ? __popc(bits[tid]) : 0;
    int sc = c;  // inclusive warp scan
#pragma unroll
    for (int o = 1; o < 32; o <<= 1) {
        int n = __shfl_up_sync(FULLM, sc, o);
        if (lane >= o) sc += n;
    }
    if (lane == 31) wsum[wid] = sc;
    __syncthreads();
    if (tid < 16) {
        int w = wsum[tid], sw = w;
#pragma unroll
        for (int o = 1; o < 16; o <<= 1) {
            int n = __shfl_up_sync(0x0000ffffu, sw, o);
            if (tid >= o) sw += n;
        }
        wsum[tid] = sw - w;               // exclusive warp offsets
        if (tid == 15) s_total = sw;
    }
    __syncthreads();
    if (tid < NWORD) {
        int p = wsum[wid] + sc - c;
        unsigned mm = bits[tid];
        while (mm) {
            int bp = __ffs(mm) - 1; mm &= mm - 1;
            s_list[p++] = tid * 32 + bp;
        }
    }
    __syncthreads();
    int cnt = s_total;
    if (q == 0 && tid == 0) g_ucnt[b] = cnt;

    // ---- this block's row range; sub-groups stride alternate rows ----
    int per = (cnt + QB - 1) / QB;
    int j0 = q * per;
    int j1 = min(cnt, j0 + per);

    const float* xb = x + (size_t)b * NN * DD;
    float4 acc = make_float4(0.f, 0.f, 0.f, 0.f);
#pragma unroll 4
    for (int j = j0 + sub; j < j1; j += 4) {
        const float4* row = reinterpret_cast<const float4*>(xb + (size_t)s_list[j] * DD);
        float4 v = row[t4];
        acc.x += v.x; acc.y += v.y; acc.z += v.z; acc.w += v.w;
    }
    s_acc[sub][t4] = acc;
    __syncthreads();

    if (sub == 0) {
        float4 a0 = s_acc[0][t4], a1 = s_acc[1][t4];
        float4 a2 = s_acc[2][t4], a3 = s_acc[3][t4];
        float4 r;
        r.x = (a0.x + a1.x) + (a2.x + a3.x);
        r.y = (a0.y + a1.y) + (a2.y + a3.y);
        r.z = (a0.z + a1.z) + (a2.z + a3.z);
        r.w = (a0.w + a1.w) + (a2.w + a3.w);
        reinterpret_cast<float4*>(g_part + (size_t)(b * QB + q) * DD)[t4] = r;
    }
}

// ===================== K4: GEMV h = emb @ W1 + b1 (float4 weights) ========
// block = (batch, otile of 64); 256 threads = 16 o4-groups x 16 k-slices(32)
__global__ void __launch_bounds__(256)
k_gemv(const float* __restrict__ W1, const float* __restrict__ b1) {
    int blk = blockIdx.x;
    int b  = blk >> 3;           // 8 otiles per batch
    int qo = blk & 7;
    int tid = threadIdx.x;
    int og = tid & 15;           // float4 output group (4 outputs)
    int ks = tid >> 4;           // k-slice of 32

    __shared__ float  s_v[DD];
    __shared__ float4 s_p[16][16];   // [kslice][ogroup]

    // emb for this batch
    float cnt = (float)g_ucnt[b];
    const float* pp = g_part + (size_t)b * QB * DD;
    for (int f = tid; f < DD; f += 256) {
        float e = 0.f;
#pragma unroll
        for (int q = 0; q < QB; q++) e += pp[q * DD + f];
        s_v[f] = e / cnt;
    }
    __syncthreads();

    // partial GEMV: 32 float4 loads per thread
    int j0 = qo * OTILE;
    const float* vv = s_v + ks * 32;
    const float* wbase = W1 + (size_t)(ks * 32) * DD + j0 + og * 4;
    float4 acc = make_float4(0.f, 0.f, 0.f, 0.f);
#pragma unroll 8
    for (int k = 0; k < 32; k++) {
        float4 w = *reinterpret_cast<const float4*>(wbase + (size_t)k * DD);
        float sv = vv[k];
        acc.x = __fmaf_rn(sv, w.x, acc.x);
        acc.y = __fmaf_rn(sv, w.y, acc.y);
        acc.z = __fmaf_rn(sv, w.z, acc.z);
        acc.w = __fmaf_rn(sv, w.w, acc.w);
    }
    s_p[ks][og] = acc;
    __syncthreads();

    if (tid < OTILE) {
        int cc = tid & 3, g = tid >> 2;
        float h = 0.f;
#pragma unroll
        for (int s = 0; s < 16; s++)
            h += reinterpret_cast<const float*>(&s_p[s][g])[cc];
        g_h[b * DD + j0 + tid] = h + b1[j0 + tid];
    }
}

// -------- block-wide sum over 512 threads --------
__device__ __forceinline__ float block_sum512(float v, float* s_red) {
    int tid = threadIdx.x;
#pragma unroll
    for (int o = 16; o; o >>= 1) v += __shfl_xor_sync(FULLM, v, o);
    if ((tid & 31) == 0) s_red[tid >> 5] = v;
    __syncthreads();
    if (tid < 16) {
        float r = s_red[tid];
#pragma unroll
        for (int o = 8; o; o >>= 1) r += __shfl_xor_sync(0x0000ffffu, r, o);
        if (tid == 0) s_red[0] = r;
    }
    __syncthreads();
    float r = s_red[0];
    __syncthreads();
    return r;
}

// ===================== K5: LN + SiLU + head ===============================
__global__ void __launch_bounds__(DD)
k_lnhead(const float* __restrict__ gamma, const float* __restrict__ beta,
         const float* __restrict__ W2, const float* __restrict__ b2,
         float* __restrict__ out) {
    int b = blockIdx.x, tid = threadIdx.x;
    __shared__ float s_red[16];
    __shared__ float s_part[16][OO];

    float h = g_h[b * DD + tid];

    float mu  = block_sum512(h, s_red) * (1.0f / DD);
    float dv  = h - mu;
    float var = block_sum512(dv * dv, s_red) * (1.0f / DD);
    float vn  = dv * rsqrtf(var + 1e-5f) * gamma[tid] + beta[tid];
    float act = vn / (1.0f + __expf(-vn));  // SiLU

    float p[OO];
#pragma unroll
    for (int o = 0; o < OO; o++) p[o] = act * W2[tid * OO + o];
#pragma unroll
    for (int o = 0; o < OO; o++)
#pragma unroll
        for (int of = 16; of; of >>= 1)
            p[o] += __shfl_xor_sync(FULLM, p[o], of);
    if ((tid & 31) == 0) {
#pragma unroll
        for (int o = 0; o < OO; o++) s_part[tid >> 5][o] = p[o];
    }
    __syncthreads();
    if (tid < OO) {
        float s = 0.f;
#pragma unroll
        for (int w = 0; w < 16; w++) s += s_part[w][tid];
        out[b * OO + tid] = s + b2[tid];
    }
}

extern "C" void kernel_launch(void* const* d_in, const int* in_sizes, int n_in,
                              void* d_out, int out_size) {
    const float* pos   = (const float*)d_in[0];
    const float* x     = (const float*)d_in[1];
    const float* lig   = (const float*)d_in[2];
    const float* W1    = (const float*)d_in[3];
    const float* b1    = (const float*)d_in[4];
    const float* gamma = (const float*)d_in[5];
    const float* beta  = (const float*)d_in[6];
    const float* W2    = (const float*)d_in[7];
    const float* b2    = (const float*)d_in[8];
    float* out = (float*)d_out;

    k_knn<<<BB * NGRP * NHALF, NCHUNK * 32>>>(pos, lig);  // 640 x 128
    k_top_merge<<<(BB * LL * 32 + 255) / 256, 256>>>();   // 400 x 256
    k_pool<<<BB * QB, DD>>>(x);                           // 512 x 512
    k_gemv<<<BB * 8, 256>>>(W1, b1);                      // 512 x 256
    k_lnhead<<<BB, DD>>>(gamma, beta, W2, b2, out);
}